// round 9
// baseline (speedup 1.0000x reference)
#include <cuda_runtime.h>
#include <cstdint>
#include <math.h>

#define NN 50000
#define EE 800000
#define F 128
#define OUTC 10
#define GG 64

// fragment-major A smem: [g 4][kt 16][lane 33pad][4]  (u32)
#define AF_SIZE (4 * 16 * 33 * 4)
// fragment-major B smem: [cg 2][ch 4][kt 16][lane 32][4] (u32)
#define BF_SIZE (2 * 4 * 16 * 32 * 4)

// ---------------- scratch (device globals; no allocation allowed) ----------
__device__ __align__(16) float g_deg[NN];
__device__ __align__(16) float g_dinv[NN];
__device__ __align__(16) float g_nself[NN];
__device__ __align__(16) int   g_cnt[NN];
__device__ __align__(16) int   g_fill[NN];
__device__ __align__(16) int   g_rowptr[NN + 1];
__device__ __align__(16) int   g_csrc[EE];
__device__ __align__(16) float g_cval[EE];
__device__ __align__(16) float g_h1[NN * F];
__device__ __align__(16) float g_h2[NN * F];
__device__ __align__(16) float g_h3[NN * OUTC];
__device__ __align__(16) float g_pool[GG * OUTC];
__device__ __align__(16) float g_pcnt[GG];
__device__ __align__(16) int   g_bsum[256];
__device__ __align__(16) uint32_t g_wf1[BF_SIZE];  // W1 in B-fragment order (tf32)
__device__ __align__(16) uint32_t g_wf2[BF_SIZE];  // W2 in B-fragment order (tf32)

// ---------------- mma helpers -----------------------------------------------
__device__ __forceinline__ uint32_t f2tf32(float f) {
    uint32_t r;
    asm("cvt.rna.tf32.f32 %0, %1;" : "=r"(r) : "f"(f));
    return r;
}
__device__ __forceinline__ void mma_tf32(float* d, const uint32_t* a, const uint32_t* b) {
    asm volatile(
        "mma.sync.aligned.m16n8k8.row.col.f32.tf32.tf32.f32 "
        "{%0,%1,%2,%3}, {%4,%5,%6,%7}, {%8,%9}, {%0,%1,%2,%3};\n"
        : "+f"(d[0]), "+f"(d[1]), "+f"(d[2]), "+f"(d[3])
        : "r"(a[0]), "r"(a[1]), "r"(a[2]), "r"(a[3]), "r"(b[0]), "r"(b[1]));
}

// ---------------- init + W-fragment precompute ------------------------------
__global__ void k_zero_wf(const float* __restrict__ W1, const float* __restrict__ W2) {
    int i = blockIdx.x * blockDim.x + threadIdx.x;
    if (i < NN) { g_deg[i] = 0.f; g_cnt[i] = 0; g_fill[i] = 0; }
    if (i < GG * OUTC) g_pool[i] = 0.f;
    if (i < GG) g_pcnt[i] = 0.f;
    if (i < 2 * BF_SIZE) {
        int sel = i >> 14;           // BF_SIZE = 16384
        int off = i & (BF_SIZE - 1);
        int pos  = off & 3;
        int lane = (off >> 2) & 31;
        int kt   = (off >> 7) & 15;
        int ch   = (off >> 11) & 3;
        int cg   = (off >> 13) & 1;
        int gid = lane >> 2, tig = lane & 3;
        int q = pos >> 1, bi = pos & 1;
        int nt = 2 * ch + q;
        int col = 64 * cg + nt * 8 + gid;
        int k = 8 * kt + tig + 4 * bi;
        float v = sel ? W2[k * F + col] : W1[k * F + col];
        uint32_t t = f2tf32(v);
        if (sel) g_wf2[off] = t; else g_wf1[off] = t;
    }
}

__global__ void k_deg(const int* __restrict__ ei, const float* __restrict__ ew) {
    int e = blockIdx.x * blockDim.x + threadIdx.x;
    if (e >= EE) return;
    int d = ei[EE + e];
    atomicAdd(&g_deg[d], ew[e]);
    atomicAdd(&g_cnt[d], 1);
}

__global__ void k_scan1() {
    __shared__ int s[256];
    int tid = threadIdx.x;
    int i = blockIdx.x * 256 + tid;
    if (i < NN) {
        float di = rsqrtf(g_deg[i] + 1.0f);
        g_dinv[i] = di;
        g_nself[i] = di * di;
    }
    int v = (i < NN) ? g_cnt[i] : 0;
    s[tid] = v; __syncthreads();
#pragma unroll
    for (int off = 1; off < 256; off <<= 1) {
        int t = (tid >= off) ? s[tid - off] : 0;
        __syncthreads();
        s[tid] += t;
        __syncthreads();
    }
    if (i < NN) g_rowptr[i] = s[tid] - v;
    if (tid == 255) g_bsum[blockIdx.x] = s[255];
}

// fused scan2+scan3
__global__ void k_scan23() {
    __shared__ int wsum[8];
    int tid = threadIdx.x, bid = blockIdx.x;
    int lane = tid & 31, wid = tid >> 5;
    int v = (tid < bid) ? g_bsum[tid] : 0;
#pragma unroll
    for (int off = 16; off; off >>= 1) v += __shfl_xor_sync(0xffffffffu, v, off);
    if (lane == 0) wsum[wid] = v;
    __syncthreads();
    if (tid == 0) {
        int t = 0;
#pragma unroll
        for (int j = 0; j < 8; j++) t += wsum[j];
        wsum[0] = t;
    }
    __syncthreads();
    int pref = wsum[0];
    int i = bid * 256 + tid;
    if (i < NN) g_rowptr[i] += pref;
    if (i == 0) g_rowptr[NN] = EE;
}

__global__ void k_fill(const int* __restrict__ ei, const float* __restrict__ ew) {
    int e = blockIdx.x * blockDim.x + threadIdx.x;
    if (e >= EE) return;
    int s = ei[e];
    int d = ei[EE + e];
    float nv = g_dinv[s] * ew[e] * g_dinv[d];
    int p = g_rowptr[d] + atomicAdd(&g_fill[d], 1);
    g_csrc[p] = s;
    g_cval[p] = nv;
}

// ---------------- tf32 mma GEMM, fragment-major smem ------------------------
// CTA = 64 rows x 128 cols; 8 warps = 4 row-groups x 2 col-halves; warp 16x64.
// Mainloop per kt per warp: 1 LDS.128 (A) + 4 LDS.128 (B) + 8 MMA.
__global__ void __launch_bounds__(256) k_gemm_mma(
    const float* __restrict__ X, const uint32_t* __restrict__ Wf,
    float* __restrict__ Y, int nrows)
{
    extern __shared__ uint32_t sm[];
    uint32_t* Af = sm;              // AF_SIZE
    uint32_t* Bf = sm + AF_SIZE;    // BF_SIZE
    int tid = threadIdx.x;
    int row0 = blockIdx.x * 64;

    // stage B: straight fragment-order copy (coalesced, L2-resident)
#pragma unroll
    for (int it = 0; it < 16; it++) {
        int i = (tid + it * 256) * 4;
        *(uint4*)&Bf[i] = *(const uint4*)&Wf[i];
    }
    // stage A: fragment scatter (tf32-converted)
#pragma unroll
    for (int it = 0; it < 8; it++) {
        int i = tid * 4 + it * 1024;       // element index (4 floats per step)
        int r = i >> 7, c = i & 127;
        float4 v = make_float4(0.f, 0.f, 0.f, 0.f);
        if (row0 + r < nrows) v = *(const float4*)&X[(row0 + r) * F + c];
        int g = r >> 4, rr = r & 15;
        int gid = rr & 7, ah = rr >> 3;
        float vv[4] = {v.x, v.y, v.z, v.w};
#pragma unroll
        for (int j = 0; j < 4; j++) {
            int k = c + j;
            int kt = k >> 3, kk = k & 7;
            int tig = kk & 3, ai = ah | ((kk >> 2) << 1);
            Af[((g * 16 + kt) * 33 + gid * 4 + tig) * 4 + ai] = f2tf32(vv[j]);
        }
    }
    __syncthreads();

    int wid = tid >> 5, lane = tid & 31;
    int gid = lane >> 2, tig = lane & 3;
    int mg = wid >> 1;            // row group 0..3
    int cg = wid & 1;             // col half 0..1

    float acc[8][4];
#pragma unroll
    for (int nt = 0; nt < 8; nt++)
#pragma unroll
        for (int j = 0; j < 4; j++) acc[nt][j] = 0.f;

#pragma unroll
    for (int kt = 0; kt < 16; kt++) {
        uint32_t a[4];
        *(uint4*)a = *(const uint4*)&Af[((mg * 16 + kt) * 33 + lane) * 4];
        uint32_t b[16];
#pragma unroll
        for (int ch = 0; ch < 4; ch++)
            *(uint4*)&b[ch * 4] = *(const uint4*)&Bf[(((cg * 4 + ch) * 16 + kt) * 32 + lane) * 4];
#pragma unroll
        for (int nt = 0; nt < 8; nt++)
            mma_tf32(acc[nt], a, &b[nt * 2]);
    }

    int r0 = row0 + mg * 16 + gid;
    int r1 = r0 + 8;
#pragma unroll
    for (int nt = 0; nt < 8; nt++) {
        int c = cg * 64 + nt * 8 + tig * 2;
        if (r0 < nrows) *(float2*)&Y[r0 * F + c] = make_float2(acc[nt][0], acc[nt][1]);
        if (r1 < nrows) *(float2*)&Y[r1 * F + c] = make_float2(acc[nt][2], acc[nt][3]);
    }
}

// ---------------- sparse aggregation, 128-wide (warp per node) --------------
__global__ void k_agg128(const float* __restrict__ H, float* __restrict__ O,
                         const float* __restrict__ bias)
{
    int gt = blockIdx.x * blockDim.x + threadIdx.x;
    int node = gt >> 5;
    int lane = gt & 31;
    const float4* H4 = (const float4*)H;

    float4 h = H4[node * 32 + lane];
    float ns = g_nself[node];
    float4 acc = make_float4(ns * h.x, ns * h.y, ns * h.z, ns * h.w);

    int p = g_rowptr[node];
    int p1 = g_rowptr[node + 1];
    int s = 0; float v = 0.f;
    if (p < p1) { s = g_csrc[p]; v = g_cval[p]; }
    while (p < p1) {
        int sn = 0; float vn = 0.f;
        if (p + 1 < p1) { sn = g_csrc[p + 1]; vn = g_cval[p + 1]; }
        float4 hs = H4[s * 32 + lane];
        acc.x += v * hs.x; acc.y += v * hs.y; acc.z += v * hs.z; acc.w += v * hs.w;
        s = sn; v = vn; p++;
    }
    float4 b = ((const float4*)bias)[lane];
    acc.x = fmaxf(acc.x + b.x, 0.f); acc.y = fmaxf(acc.y + b.y, 0.f);
    acc.z = fmaxf(acc.z + b.z, 0.f); acc.w = fmaxf(acc.w + b.w, 0.f);
    ((float4*)O)[node * 32 + lane] = acc;
}

// ---------------- agg2 fused with output GEMM -------------------------------
__global__ void k_agg_out(const float* __restrict__ H,
                          const float* __restrict__ bias,
                          const float* __restrict__ W3)
{
    __shared__ __align__(16) float Wt[OUTC * F];  // [c][k]
    int tid = threadIdx.x;
    for (int i = tid; i < OUTC * F; i += blockDim.x) {
        int c = i >> 7, k = i & 127;
        Wt[i] = W3[k * OUTC + c];
    }
    __syncthreads();

    int gt = blockIdx.x * blockDim.x + tid;
    int node = gt >> 5;
    int lane = gt & 31;
    const float4* H4 = (const float4*)H;

    float4 h = H4[node * 32 + lane];
    float ns = g_nself[node];
    float4 acc = make_float4(ns * h.x, ns * h.y, ns * h.z, ns * h.w);

    int p = g_rowptr[node];
    int p1 = g_rowptr[node + 1];
    int s = 0; float v = 0.f;
    if (p < p1) { s = g_csrc[p]; v = g_cval[p]; }
    while (p < p1) {
        int sn = 0; float vn = 0.f;
        if (p + 1 < p1) { sn = g_csrc[p + 1]; vn = g_cval[p + 1]; }
        float4 hs = H4[s * 32 + lane];
        acc.x += v * hs.x; acc.y += v * hs.y; acc.z += v * hs.z; acc.w += v * hs.w;
        s = sn; v = vn; p++;
    }
    float4 b = ((const float4*)bias)[lane];
    acc.x = fmaxf(acc.x + b.x, 0.f); acc.y = fmaxf(acc.y + b.y, 0.f);
    acc.z = fmaxf(acc.z + b.z, 0.f); acc.w = fmaxf(acc.w + b.w, 0.f);

    float o[OUTC];
#pragma unroll
    for (int c = 0; c < OUTC; c++) {
        float4 wv = ((const float4*)Wt)[c * 32 + lane];
        o[c] = acc.x * wv.x + acc.y * wv.y + acc.z * wv.z + acc.w * wv.w;
    }
#pragma unroll
    for (int off = 16; off; off >>= 1)
#pragma unroll
        for (int c = 0; c < OUTC; c++)
            o[c] += __shfl_xor_sync(0xffffffffu, o[c], off);
    if (lane == 0) {
#pragma unroll
        for (int c = 0; c < OUTC; c++) g_h3[node * OUTC + c] = o[c];
    }
}

// ---------------- sparse agg 10-wide + bias + pooling (fused) ---------------
__global__ void k_agg10_pool(const float* __restrict__ b3,
                             const int* __restrict__ batch)
{
    __shared__ float sp[GG * OUTC];
    __shared__ float sc[GG];
    int tid = threadIdx.x;
    for (int j = tid; j < GG * OUTC; j += blockDim.x) sp[j] = 0.f;
    for (int j = tid; j < GG; j += blockDim.x) sc[j] = 0.f;
    __syncthreads();

    int gt = blockIdx.x * blockDim.x + tid;
    int node = gt >> 5;
    int lane = gt & 31;

    float acc = 0.f;
    if (lane < OUTC) acc = g_nself[node] * g_h3[node * OUTC + lane];
    int p = g_rowptr[node];
    int p1 = g_rowptr[node + 1];
    for (; p < p1; p++) {
        int s = g_csrc[p];
        float v = g_cval[p];
        if (lane < OUTC) acc += v * g_h3[s * OUTC + lane];
    }
    int g = batch[node];
    if (lane < OUTC) atomicAdd(&sp[g * OUTC + lane], acc + b3[lane]);
    if (lane == OUTC) atomicAdd(&sc[g], 1.0f);
    __syncthreads();

    for (int j = tid; j < GG * OUTC; j += blockDim.x)
        if (sp[j] != 0.f) atomicAdd(&g_pool[j], sp[j]);
    for (int j = tid; j < GG; j += blockDim.x)
        if (sc[j] != 0.f) atomicAdd(&g_pcnt[j], sc[j]);
}

// ---------------- mean + log_softmax ----------------------------------------
__global__ void k_final(float* __restrict__ out)
{
    int g = threadIdx.x;
    if (g >= GG) return;
    float cnt = fmaxf(g_pcnt[g], 1.0f);
    float v[OUTC];
    float m = -1e30f;
#pragma unroll
    for (int c = 0; c < OUTC; c++) {
        v[c] = g_pool[g * OUTC + c] / cnt;
        m = fmaxf(m, v[c]);
    }
    float s = 0.f;
#pragma unroll
    for (int c = 0; c < OUTC; c++) s += expf(v[c] - m);
    float l = logf(s) + m;
#pragma unroll
    for (int c = 0; c < OUTC; c++) out[g * OUTC + c] = v[c] - l;
}

// ---------------- launch ----------------------------------------------------
extern "C" void kernel_launch(void* const* d_in, const int* in_sizes, int n_in,
                              void* d_out, int out_size)
{
    const float* x     = (const float*)d_in[0];
    const int*   ei    = (const int*)  d_in[1];
    const float* ew    = (const float*)d_in[2];
    const int*   batch = (const int*)  d_in[3];
    const float* W1    = (const float*)d_in[4];
    const float* b1    = (const float*)d_in[5];
    const float* W2    = (const float*)d_in[6];
    const float* b2    = (const float*)d_in[7];
    const float* W3    = (const float*)d_in[8];
    const float* b3    = (const float*)d_in[9];
    float* out = (float*)d_out;

    const int SMEM_MMA = (AF_SIZE + BF_SIZE) * sizeof(uint32_t);  // 99328
    cudaFuncSetAttribute(k_gemm_mma, cudaFuncAttributeMaxDynamicSharedMemorySize, SMEM_MMA);

    float *h1p, *h2p;
    uint32_t *wf1p, *wf2p;
    cudaGetSymbolAddress((void**)&h1p, g_h1);
    cudaGetSymbolAddress((void**)&h2p, g_h2);
    cudaGetSymbolAddress((void**)&wf1p, g_wf1);
    cudaGetSymbolAddress((void**)&wf2p, g_wf2);

    const int nBlkN = (NN + 255) / 256;          // 196
    const int nBlkE = (EE + 255) / 256;          // 3125
    const int nBlkW = (NN * 32) / 256;           // 6250
    const int nBlkT = (NN + 63) / 64;            // 782 (mma gemm)

    k_zero_wf<<<nBlkN, 256>>>(W1, W2);                           // my 1
    k_deg  <<<nBlkE, 256>>>(ei, ew);                             // my 2
    k_scan1<<<nBlkN, 256>>>();                                   // my 3
    k_gemm_mma<<<nBlkT, 256, SMEM_MMA>>>(x, wf1p, h1p, NN);      // my 4 <- ncu sample
    k_scan23<<<nBlkN, 256>>>();                                  // my 5
    k_fill <<<nBlkE, 256>>>(ei, ew);                             // my 6

    k_agg128<<<nBlkW, 256>>>(h1p, h2p, b1);                      // my 7
    k_gemm_mma<<<nBlkT, 256, SMEM_MMA>>>(h2p, wf2p, h1p, NN);    // my 8
    k_agg_out<<<nBlkW, 256>>>(h1p, b2, W3);                      // my 9
    k_agg10_pool<<<nBlkW, 256>>>(b3, batch);                     // my 10
    k_final<<<1, 64>>>(out);                                     // my 11
}

// round 10
// speedup vs baseline: 1.5467x; 1.5467x over previous
#include <cuda_runtime.h>
#include <cuda_fp16.h>
#include <cstdint>
#include <math.h>

#define NN 50000
#define EE 800000
#define F 128
#define OUTC 10
#define GG 64

// fragment-major A smem: [g 4][kt 16][lane 33pad][4]  (u32)
#define AF_SIZE (4 * 16 * 33 * 4)
// fragment-major B smem: [cg 2][ch 4][kt 16][lane 32][4] (u32)
#define BF_SIZE (2 * 4 * 16 * 32 * 4)

// ---------------- scratch (device globals; no allocation allowed) ----------
__device__ __align__(16) float g_deg[NN];
__device__ __align__(16) float g_dinv[NN];
__device__ __align__(16) float g_nself[NN];
__device__ __align__(16) int   g_cnt[NN];
__device__ __align__(16) int   g_fill[NN];
__device__ __align__(16) int   g_rowptr[NN + 1];
__device__ __align__(16) int   g_csrc[EE];
__device__ __align__(16) float g_cval[EE];
__device__ __align__(16) __half g_h1[NN * F];   // fp16 hidden states
__device__ __align__(16) __half g_h2[NN * F];
__device__ __align__(16) float g_h3[NN * OUTC];
__device__ __align__(16) float g_pool[GG * OUTC];
__device__ __align__(16) float g_pcnt[GG];
__device__ __align__(16) int   g_bsum[256];
__device__ __align__(16) uint32_t g_wf1[BF_SIZE];  // W1 in B-fragment order (tf32)
__device__ __align__(16) uint32_t g_wf2[BF_SIZE];  // W2 in B-fragment order (tf32)

// ---------------- mma helpers -----------------------------------------------
__device__ __forceinline__ uint32_t f2tf32(float f) {
    uint32_t r;
    asm("cvt.rna.tf32.f32 %0, %1;" : "=r"(r) : "f"(f));
    return r;
}
__device__ __forceinline__ void mma_tf32(float* d, const uint32_t* a, const uint32_t* b) {
    asm volatile(
        "mma.sync.aligned.m16n8k8.row.col.f32.tf32.tf32.f32 "
        "{%0,%1,%2,%3}, {%4,%5,%6,%7}, {%8,%9}, {%0,%1,%2,%3};\n"
        : "+f"(d[0]), "+f"(d[1]), "+f"(d[2]), "+f"(d[3])
        : "r"(a[0]), "r"(a[1]), "r"(a[2]), "r"(a[3]), "r"(b[0]), "r"(b[1]));
}

// ---------------- init + W-fragment precompute ------------------------------
__global__ void k_zero_wf(const float* __restrict__ W1, const float* __restrict__ W2) {
    int i = blockIdx.x * blockDim.x + threadIdx.x;
    if (i < NN) { g_deg[i] = 0.f; g_cnt[i] = 0; g_fill[i] = 0; }
    if (i < GG * OUTC) g_pool[i] = 0.f;
    if (i < GG) g_pcnt[i] = 0.f;
    if (i < 2 * BF_SIZE) {
        int sel = i >> 14;           // BF_SIZE = 16384
        int off = i & (BF_SIZE - 1);
        int pos  = off & 3;
        int lane = (off >> 2) & 31;
        int kt   = (off >> 7) & 15;
        int ch   = (off >> 11) & 3;
        int cg   = (off >> 13) & 1;
        int gid = lane >> 2, tig = lane & 3;
        int q = pos >> 1, bi = pos & 1;
        int nt = 2 * ch + q;
        int col = 64 * cg + nt * 8 + gid;
        int k = 8 * kt + tig + 4 * bi;
        float v = sel ? W2[k * F + col] : W1[k * F + col];
        uint32_t t = f2tf32(v);
        if (sel) g_wf2[off] = t; else g_wf1[off] = t;
    }
}

__global__ void k_deg(const int* __restrict__ ei, const float* __restrict__ ew) {
    int e = blockIdx.x * blockDim.x + threadIdx.x;
    if (e >= EE) return;
    int d = ei[EE + e];
    atomicAdd(&g_deg[d], ew[e]);
    atomicAdd(&g_cnt[d], 1);
}

__global__ void k_scan1() {
    __shared__ int s[256];
    int tid = threadIdx.x;
    int i = blockIdx.x * 256 + tid;
    if (i < NN) {
        float di = rsqrtf(g_deg[i] + 1.0f);
        g_dinv[i] = di;
        g_nself[i] = di * di;
    }
    int v = (i < NN) ? g_cnt[i] : 0;
    s[tid] = v; __syncthreads();
#pragma unroll
    for (int off = 1; off < 256; off <<= 1) {
        int t = (tid >= off) ? s[tid - off] : 0;
        __syncthreads();
        s[tid] += t;
        __syncthreads();
    }
    if (i < NN) g_rowptr[i] = s[tid] - v;
    if (tid == 255) g_bsum[blockIdx.x] = s[255];
}

// fused scan2+scan3
__global__ void k_scan23() {
    __shared__ int wsum[8];
    int tid = threadIdx.x, bid = blockIdx.x;
    int lane = tid & 31, wid = tid >> 5;
    int v = (tid < bid) ? g_bsum[tid] : 0;
#pragma unroll
    for (int off = 16; off; off >>= 1) v += __shfl_xor_sync(0xffffffffu, v, off);
    if (lane == 0) wsum[wid] = v;
    __syncthreads();
    if (tid == 0) {
        int t = 0;
#pragma unroll
        for (int j = 0; j < 8; j++) t += wsum[j];
        wsum[0] = t;
    }
    __syncthreads();
    int pref = wsum[0];
    int i = bid * 256 + tid;
    if (i < NN) g_rowptr[i] += pref;
    if (i == 0) g_rowptr[NN] = EE;
}

__global__ void k_fill(const int* __restrict__ ei, const float* __restrict__ ew) {
    int e = blockIdx.x * blockDim.x + threadIdx.x;
    if (e >= EE) return;
    int s = ei[e];
    int d = ei[EE + e];
    float nv = g_dinv[s] * ew[e] * g_dinv[d];
    int p = g_rowptr[d] + atomicAdd(&g_fill[d], 1);
    g_csrc[p] = s;
    g_cval[p] = nv;
}

// ---------------- tf32 mma GEMM, fragment-major smem, fp16 output -----------
// CTA = 64 rows x 128 cols; 8 warps = 4 row-groups x 2 col-halves; warp 16x64.
// X input is fp32 (x_is_half=0) or fp16 (x_is_half=1). Y output is fp16.
__global__ void __launch_bounds__(256) k_gemm_mma(
    const void* __restrict__ Xv, const uint32_t* __restrict__ Wf,
    __half* __restrict__ Y, int nrows, int x_is_half)
{
    extern __shared__ uint32_t sm[];
    uint32_t* Af = sm;              // AF_SIZE
    uint32_t* Bf = sm + AF_SIZE;    // BF_SIZE
    int tid = threadIdx.x;
    int row0 = blockIdx.x * 64;

    // stage B: straight fragment-order copy (coalesced, L2-resident)
#pragma unroll
    for (int it = 0; it < 16; it++) {
        int i = (tid + it * 256) * 4;
        *(uint4*)&Bf[i] = *(const uint4*)&Wf[i];
    }
    // stage A: fragment scatter (tf32-converted)
    const float*  Xf = (const float*)Xv;
    const __half* Xh = (const __half*)Xv;
#pragma unroll
    for (int it = 0; it < 8; it++) {
        int i = tid * 4 + it * 1024;       // element index (4 per step)
        int r = i >> 7, c = i & 127;
        float4 v = make_float4(0.f, 0.f, 0.f, 0.f);
        if (row0 + r < nrows) {
            if (x_is_half) {
                uint2 raw = *(const uint2*)&Xh[(row0 + r) * F + c];
                float2 f0 = __half22float2(*(__half2*)&raw.x);
                float2 f1 = __half22float2(*(__half2*)&raw.y);
                v = make_float4(f0.x, f0.y, f1.x, f1.y);
            } else {
                v = *(const float4*)&Xf[(row0 + r) * F + c];
            }
        }
        int g = r >> 4, rr = r & 15;
        int gid = rr & 7, ah = rr >> 3;
        float vv[4] = {v.x, v.y, v.z, v.w};
#pragma unroll
        for (int j = 0; j < 4; j++) {
            int k = c + j;
            int kt = k >> 3, kk = k & 7;
            int tig = kk & 3, ai = ah | ((kk >> 2) << 1);
            Af[((g * 16 + kt) * 33 + gid * 4 + tig) * 4 + ai] = f2tf32(vv[j]);
        }
    }
    __syncthreads();

    int wid = tid >> 5, lane = tid & 31;
    int gid = lane >> 2, tig = lane & 3;
    int mg = wid >> 1;            // row group 0..3
    int cg = wid & 1;             // col half 0..1

    float acc[8][4];
#pragma unroll
    for (int nt = 0; nt < 8; nt++)
#pragma unroll
        for (int j = 0; j < 4; j++) acc[nt][j] = 0.f;

#pragma unroll
    for (int kt = 0; kt < 16; kt++) {
        uint32_t a[4];
        *(uint4*)a = *(const uint4*)&Af[((mg * 16 + kt) * 33 + lane) * 4];
        uint32_t b[16];
#pragma unroll
        for (int ch = 0; ch < 4; ch++)
            *(uint4*)&b[ch * 4] = *(const uint4*)&Bf[(((cg * 4 + ch) * 16 + kt) * 32 + lane) * 4];
#pragma unroll
        for (int nt = 0; nt < 8; nt++)
            mma_tf32(acc[nt], a, &b[nt * 2]);
    }

    int r0 = row0 + mg * 16 + gid;
    int r1 = r0 + 8;
    __half2* Y2 = (__half2*)Y;
#pragma unroll
    for (int nt = 0; nt < 8; nt++) {
        int c = cg * 64 + nt * 8 + tig * 2;     // even
        if (r0 < nrows) Y2[r0 * 64 + (c >> 1)] = __floats2half2_rn(acc[nt][0], acc[nt][1]);
        if (r1 < nrows) Y2[r1 * 64 + (c >> 1)] = __floats2half2_rn(acc[nt][2], acc[nt][3]);
    }
}

// ---------------- sparse aggregation, 128-wide fp16 (warp per node) ---------
__global__ void k_agg128(const __half* __restrict__ H, __half* __restrict__ O,
                         const float* __restrict__ bias)
{
    int gt = blockIdx.x * blockDim.x + threadIdx.x;
    int node = gt >> 5;
    int lane = gt & 31;
    const uint2* H2 = (const uint2*)H;   // per lane: 4 halves (cols lane*4..lane*4+3)

    uint2 hv = H2[node * 32 + lane];
    float2 f0 = __half22float2(*(__half2*)&hv.x);
    float2 f1 = __half22float2(*(__half2*)&hv.y);
    float ns = g_nself[node];
    float4 acc = make_float4(ns * f0.x, ns * f0.y, ns * f1.x, ns * f1.y);

    int p = g_rowptr[node];
    int p1 = g_rowptr[node + 1];
    int s = 0; float v = 0.f;
    if (p < p1) { s = g_csrc[p]; v = g_cval[p]; }
    while (p < p1) {
        int sn = 0; float vn = 0.f;
        if (p + 1 < p1) { sn = g_csrc[p + 1]; vn = g_cval[p + 1]; }
        uint2 hs = H2[s * 32 + lane];
        float2 s0 = __half22float2(*(__half2*)&hs.x);
        float2 s1 = __half22float2(*(__half2*)&hs.y);
        acc.x += v * s0.x; acc.y += v * s0.y; acc.z += v * s1.x; acc.w += v * s1.y;
        s = sn; v = vn; p++;
    }
    float4 b = ((const float4*)bias)[lane];
    acc.x = fmaxf(acc.x + b.x, 0.f); acc.y = fmaxf(acc.y + b.y, 0.f);
    acc.z = fmaxf(acc.z + b.z, 0.f); acc.w = fmaxf(acc.w + b.w, 0.f);
    uint2 ov;
    *(__half2*)&ov.x = __floats2half2_rn(acc.x, acc.y);
    *(__half2*)&ov.y = __floats2half2_rn(acc.z, acc.w);
    ((uint2*)O)[node * 32 + lane] = ov;
}

// ---------------- agg2 fused with output GEMM (fp16 gather) -----------------
__global__ void k_agg_out(const __half* __restrict__ H,
                          const float* __restrict__ bias,
                          const float* __restrict__ W3)
{
    __shared__ __align__(16) float Wt[OUTC * F];  // [c][k]
    int tid = threadIdx.x;
    for (int i = tid; i < OUTC * F; i += blockDim.x) {
        int c = i >> 7, k = i & 127;
        Wt[i] = W3[k * OUTC + c];
    }
    __syncthreads();

    int gt = blockIdx.x * blockDim.x + tid;
    int node = gt >> 5;
    int lane = gt & 31;
    const uint2* H2 = (const uint2*)H;

    uint2 hv = H2[node * 32 + lane];
    float2 f0 = __half22float2(*(__half2*)&hv.x);
    float2 f1 = __half22float2(*(__half2*)&hv.y);
    float ns = g_nself[node];
    float4 acc = make_float4(ns * f0.x, ns * f0.y, ns * f1.x, ns * f1.y);

    int p = g_rowptr[node];
    int p1 = g_rowptr[node + 1];
    int s = 0; float v = 0.f;
    if (p < p1) { s = g_csrc[p]; v = g_cval[p]; }
    while (p < p1) {
        int sn = 0; float vn = 0.f;
        if (p + 1 < p1) { sn = g_csrc[p + 1]; vn = g_cval[p + 1]; }
        uint2 hs = H2[s * 32 + lane];
        float2 s0 = __half22float2(*(__half2*)&hs.x);
        float2 s1 = __half22float2(*(__half2*)&hs.y);
        acc.x += v * s0.x; acc.y += v * s0.y; acc.z += v * s1.x; acc.w += v * s1.y;
        s = sn; v = vn; p++;
    }
    float4 b = ((const float4*)bias)[lane];
    acc.x = fmaxf(acc.x + b.x, 0.f); acc.y = fmaxf(acc.y + b.y, 0.f);
    acc.z = fmaxf(acc.z + b.z, 0.f); acc.w = fmaxf(acc.w + b.w, 0.f);

    float o[OUTC];
#pragma unroll
    for (int c = 0; c < OUTC; c++) {
        float4 wv = ((const float4*)Wt)[c * 32 + lane];
        o[c] = acc.x * wv.x + acc.y * wv.y + acc.z * wv.z + acc.w * wv.w;
    }
#pragma unroll
    for (int off = 16; off; off >>= 1)
#pragma unroll
        for (int c = 0; c < OUTC; c++)
            o[c] += __shfl_xor_sync(0xffffffffu, o[c], off);
    if (lane == 0) {
#pragma unroll
        for (int c = 0; c < OUTC; c++) g_h3[node * OUTC + c] = o[c];
    }
}

// ---------------- sparse agg 10-wide + bias + pooling (fused) ---------------
__global__ void k_agg10_pool(const float* __restrict__ b3,
                             const int* __restrict__ batch)
{
    __shared__ float sp[GG * OUTC];
    __shared__ float sc[GG];
    int tid = threadIdx.x;
    for (int j = tid; j < GG * OUTC; j += blockDim.x) sp[j] = 0.f;
    for (int j = tid; j < GG; j += blockDim.x) sc[j] = 0.f;
    __syncthreads();

    int gt = blockIdx.x * blockDim.x + tid;
    int node = gt >> 5;
    int lane = gt & 31;

    float acc = 0.f;
    if (lane < OUTC) acc = g_nself[node] * g_h3[node * OUTC + lane];
    int p = g_rowptr[node];
    int p1 = g_rowptr[node + 1];
    for (; p < p1; p++) {
        int s = g_csrc[p];
        float v = g_cval[p];
        if (lane < OUTC) acc += v * g_h3[s * OUTC + lane];
    }
    int g = batch[node];
    if (lane < OUTC) atomicAdd(&sp[g * OUTC + lane], acc + b3[lane]);
    if (lane == OUTC) atomicAdd(&sc[g], 1.0f);
    __syncthreads();

    for (int j = tid; j < GG * OUTC; j += blockDim.x)
        if (sp[j] != 0.f) atomicAdd(&g_pool[j], sp[j]);
    for (int j = tid; j < GG; j += blockDim.x)
        if (sc[j] != 0.f) atomicAdd(&g_pcnt[j], sc[j]);
}

// ---------------- mean + log_softmax ----------------------------------------
__global__ void k_final(float* __restrict__ out)
{
    int g = threadIdx.x;
    if (g >= GG) return;
    float cnt = fmaxf(g_pcnt[g], 1.0f);
    float v[OUTC];
    float m = -1e30f;
#pragma unroll
    for (int c = 0; c < OUTC; c++) {
        v[c] = g_pool[g * OUTC + c] / cnt;
        m = fmaxf(m, v[c]);
    }
    float s = 0.f;
#pragma unroll
    for (int c = 0; c < OUTC; c++) s += expf(v[c] - m);
    float l = logf(s) + m;
#pragma unroll
    for (int c = 0; c < OUTC; c++) out[g * OUTC + c] = v[c] - l;
}

// ---------------- launch ----------------------------------------------------
extern "C" void kernel_launch(void* const* d_in, const int* in_sizes, int n_in,
                              void* d_out, int out_size)
{
    const float* x     = (const float*)d_in[0];
    const int*   ei    = (const int*)  d_in[1];
    const float* ew    = (const float*)d_in[2];
    const int*   batch = (const int*)  d_in[3];
    const float* W1    = (const float*)d_in[4];
    const float* b1    = (const float*)d_in[5];
    const float* W2    = (const float*)d_in[6];
    const float* b2    = (const float*)d_in[7];
    const float* W3    = (const float*)d_in[8];
    const float* b3    = (const float*)d_in[9];
    float* out = (float*)d_out;

    const int SMEM_MMA = (AF_SIZE + BF_SIZE) * sizeof(uint32_t);  // 99328
    cudaFuncSetAttribute(k_gemm_mma, cudaFuncAttributeMaxDynamicSharedMemorySize, SMEM_MMA);

    __half *h1p, *h2p;
    uint32_t *wf1p, *wf2p;
    cudaGetSymbolAddress((void**)&h1p, g_h1);
    cudaGetSymbolAddress((void**)&h2p, g_h2);
    cudaGetSymbolAddress((void**)&wf1p, g_wf1);
    cudaGetSymbolAddress((void**)&wf2p, g_wf2);

    const int nBlkN = (NN + 255) / 256;          // 196
    const int nBlkE = (EE + 255) / 256;          // 3125
    const int nBlkW = (NN * 32) / 256;           // 6250
    const int nBlkT = (NN + 63) / 64;            // 782 (mma gemm)

    k_zero_wf<<<nBlkN, 256>>>(W1, W2);                           // my 1
    k_deg  <<<nBlkE, 256>>>(ei, ew);                             // my 2
    k_scan1<<<nBlkN, 256>>>();                                   // my 3
    k_gemm_mma<<<nBlkT, 256, SMEM_MMA>>>(x, wf1p, h1p, NN, 0);   // my 4 <- ncu sample
    k_scan23<<<nBlkN, 256>>>();                                  // my 5
    k_fill <<<nBlkE, 256>>>(ei, ew);                             // my 6

    k_agg128<<<nBlkW, 256>>>(h1p, h2p, b1);                      // my 7
    k_gemm_mma<<<nBlkT, 256, SMEM_MMA>>>(h2p, wf2p, h1p, NN, 1); // my 8
    k_agg_out<<<nBlkW, 256>>>(h1p, b2, W3);                      // my 9
    k_agg10_pool<<<nBlkW, 256>>>(b3, batch);                     // my 10
    k_final<<<1, 64>>>(out);                                     // my 11
}

// round 11
// speedup vs baseline: 1.6839x; 1.0887x over previous
#include <cuda_runtime.h>
#include <cuda_fp16.h>
#include <cstdint>
#include <math.h>

#define NN 50000
#define EE 800000
#define F 128
#define OUTC 10
#define GG 64

// fp16-fragment A smem: [g 4][kt 8][132 u32 (33*4 pad)]
#define AF_SIZE (4 * 8 * 132)
// fp16-fragment B smem: [cg 2][ch 4][kt 8][lane 32][4] (u32)
#define BF_SIZE (2 * 4 * 8 * 32 * 4)

// ---------------- scratch (device globals; no allocation allowed) ----------
__device__ __align__(16) float g_deg[NN];
__device__ __align__(16) float g_dinv[NN];
__device__ __align__(16) float g_nself[NN];
__device__ __align__(16) int   g_cnt[NN];
__device__ __align__(16) int   g_fill[NN];
__device__ __align__(16) int   g_rowptr[NN + 1];
__device__ __align__(16) int   g_csrc[EE];
__device__ __align__(16) float g_cval[EE];
__device__ __align__(16) __half g_h1[NN * F];   // fp16 hidden states
__device__ __align__(16) __half g_h2[NN * F];
__device__ __align__(16) float g_h3[NN * OUTC];
__device__ __align__(16) float g_pool[GG * OUTC];
__device__ __align__(16) float g_pcnt[GG];
__device__ __align__(16) int   g_bsum[256];
__device__ __align__(16) uint32_t g_wf1[BF_SIZE];  // W1 in fp16 B-fragment order
__device__ __align__(16) uint32_t g_wf2[BF_SIZE];  // W2 in fp16 B-fragment order

// ---------------- mma helpers -----------------------------------------------
__device__ __forceinline__ void mma_f16(float* d, const uint32_t* a, const uint32_t* b) {
    asm volatile(
        "mma.sync.aligned.m16n8k16.row.col.f32.f16.f16.f32 "
        "{%0,%1,%2,%3}, {%4,%5,%6,%7}, {%8,%9}, {%0,%1,%2,%3};\n"
        : "+f"(d[0]), "+f"(d[1]), "+f"(d[2]), "+f"(d[3])
        : "r"(a[0]), "r"(a[1]), "r"(a[2]), "r"(a[3]), "r"(b[0]), "r"(b[1]));
}
__device__ __forceinline__ uint32_t packh2(float lo, float hi) {
    __half2 h = __floats2half2_rn(lo, hi);
    return *(uint32_t*)&h;
}

// ---------------- init + W-fragment precompute (fp16) -----------------------
__global__ void k_zero_wf(const float* __restrict__ W1, const float* __restrict__ W2) {
    int i = blockIdx.x * blockDim.x + threadIdx.x;
    if (i < NN) { g_deg[i] = 0.f; g_cnt[i] = 0; g_fill[i] = 0; }
    if (i < GG * OUTC) g_pool[i] = 0.f;
    if (i < GG) g_pcnt[i] = 0.f;
    if (i < 2 * BF_SIZE) {                 // BF_SIZE = 8192
        int sel = i >> 13;
        int off = i & (BF_SIZE - 1);
        int pos  = off & 3;
        int lane = (off >> 2) & 31;
        int kt   = (off >> 7) & 7;
        int ch   = (off >> 10) & 3;
        int cg   = (off >> 12) & 1;
        int gid = lane >> 2, tig = lane & 3;
        int nt = 2 * ch + (pos >> 1);
        int bi = pos & 1;
        int col = 64 * cg + 8 * nt + gid;
        int k = 16 * kt + 8 * bi + 2 * tig;
        const float* W = sel ? W2 : W1;
        uint32_t u = packh2(W[k * F + col], W[(k + 1) * F + col]);
        if (sel) g_wf2[off] = u; else g_wf1[off] = u;
    }
}

__global__ void k_deg(const int* __restrict__ ei, const float* __restrict__ ew) {
    int e = blockIdx.x * blockDim.x + threadIdx.x;
    if (e >= EE) return;
    int d = ei[EE + e];
    atomicAdd(&g_deg[d], ew[e]);
    atomicAdd(&g_cnt[d], 1);
}

__global__ void k_scan1() {
    __shared__ int s[256];
    int tid = threadIdx.x;
    int i = blockIdx.x * 256 + tid;
    if (i < NN) {
        float di = rsqrtf(g_deg[i] + 1.0f);
        g_dinv[i] = di;
        g_nself[i] = di * di;
    }
    int v = (i < NN) ? g_cnt[i] : 0;
    s[tid] = v; __syncthreads();
#pragma unroll
    for (int off = 1; off < 256; off <<= 1) {
        int t = (tid >= off) ? s[tid - off] : 0;
        __syncthreads();
        s[tid] += t;
        __syncthreads();
    }
    if (i < NN) g_rowptr[i] = s[tid] - v;
    if (tid == 255) g_bsum[blockIdx.x] = s[255];
}

// fused scan2+scan3
__global__ void k_scan23() {
    __shared__ int wsum[8];
    int tid = threadIdx.x, bid = blockIdx.x;
    int lane = tid & 31, wid = tid >> 5;
    int v = (tid < bid) ? g_bsum[tid] : 0;
#pragma unroll
    for (int off = 16; off; off >>= 1) v += __shfl_xor_sync(0xffffffffu, v, off);
    if (lane == 0) wsum[wid] = v;
    __syncthreads();
    if (tid == 0) {
        int t = 0;
#pragma unroll
        for (int j = 0; j < 8; j++) t += wsum[j];
        wsum[0] = t;
    }
    __syncthreads();
    int pref = wsum[0];
    int i = bid * 256 + tid;
    if (i < NN) g_rowptr[i] += pref;
    if (i == 0) g_rowptr[NN] = EE;
}

__global__ void k_fill(const int* __restrict__ ei, const float* __restrict__ ew) {
    int e = blockIdx.x * blockDim.x + threadIdx.x;
    if (e >= EE) return;
    int s = ei[e];
    int d = ei[EE + e];
    float nv = g_dinv[s] * ew[e] * g_dinv[d];
    int p = g_rowptr[d] + atomicAdd(&g_fill[d], 1);
    g_csrc[p] = s;
    g_cval[p] = nv;
}

// ---------------- fp16 mma GEMM, fragment-major smem ------------------------
// CTA = 64 rows x 128 cols; 8 warps = 4 row-groups x 2 col-halves; warp 16x64.
// Mainloop per kt(8): 1 LDS.128 (A) + 4 LDS.128 (B) + 8 MMA (m16n8k16).
__global__ void __launch_bounds__(256) k_gemm_mma(
    const void* __restrict__ Xv, const uint32_t* __restrict__ Wf,
    __half* __restrict__ Y, int nrows, int x_is_half)
{
    extern __shared__ uint32_t sm[];
    uint32_t* Af = sm;              // AF_SIZE
    uint32_t* Bf = sm + AF_SIZE;    // BF_SIZE
    int tid = threadIdx.x;
    int row0 = blockIdx.x * 64;

    // stage B: straight fragment-order copy (coalesced, L2-resident)
#pragma unroll
    for (int it = 0; it < 8; it++) {
        int i = (tid + it * 256) * 4;
        *(uint4*)&Bf[i] = *(const uint4*)&Wf[i];
    }
    // stage A: fp16 fragment scatter. 4096 u32 total, 16 per thread.
    const float*  Xf = (const float*)Xv;
    const uint32_t* Xh = (const uint32_t*)Xv;   // fp16 pairs, 64 per row
#pragma unroll
    for (int it = 0; it < 16; it++) {
        int j = tid + it * 256;            // u32 index 0..4095
        int aidx = j & 3;
        int lfr  = (j >> 2) & 31;
        int kt   = (j >> 7) & 7;
        int g    = (j >> 10) & 3;
        int gid = lfr >> 2, tig = lfr & 3;
        int row = row0 + g * 16 + gid + 8 * (aidx & 1);
        int k = 16 * kt + 8 * (aidx >> 1) + 2 * tig;
        uint32_t u = 0;
        if (row < nrows) {
            if (x_is_half) {
                u = Xh[row * 64 + (k >> 1)];
            } else {
                float2 v = *(const float2*)&Xf[row * F + k];
                u = packh2(v.x, v.y);
            }
        }
        Af[(g * 8 + kt) * 132 + lfr * 4 + aidx] = u;
    }
    __syncthreads();

    int wid = tid >> 5, lane = tid & 31;
    int gid = lane >> 2, tig = lane & 3;
    int mg = wid >> 1;            // row group 0..3
    int cg = wid & 1;             // col half 0..1

    float acc[8][4];
#pragma unroll
    for (int nt = 0; nt < 8; nt++)
#pragma unroll
        for (int j = 0; j < 4; j++) acc[nt][j] = 0.f;

#pragma unroll
    for (int kt = 0; kt < 8; kt++) {
        uint32_t a[4];
        *(uint4*)a = *(const uint4*)&Af[(mg * 8 + kt) * 132 + lane * 4];
#pragma unroll
        for (int ch = 0; ch < 4; ch++) {
            uint32_t b[4];
            *(uint4*)b = *(const uint4*)&Bf[(((cg * 4 + ch) * 8 + kt) * 32 + lane) * 4];
            mma_f16(acc[2 * ch],     a, &b[0]);
            mma_f16(acc[2 * ch + 1], a, &b[2]);
        }
    }

    int r0 = row0 + mg * 16 + gid;
    int r1 = r0 + 8;
    __half2* Y2 = (__half2*)Y;
#pragma unroll
    for (int nt = 0; nt < 8; nt++) {
        int c = cg * 64 + nt * 8 + tig * 2;     // even
        if (r0 < nrows) Y2[r0 * 64 + (c >> 1)] = __floats2half2_rn(acc[nt][0], acc[nt][1]);
        if (r1 < nrows) Y2[r1 * 64 + (c >> 1)] = __floats2half2_rn(acc[nt][2], acc[nt][3]);
    }
}

// ---------------- sparse aggregation, 128-wide fp16 (warp per node) ---------
__global__ void k_agg128(const __half* __restrict__ H, __half* __restrict__ O,
                         const float* __restrict__ bias)
{
    int gt = blockIdx.x * blockDim.x + threadIdx.x;
    int node = gt >> 5;
    int lane = gt & 31;
    const uint2* H2 = (const uint2*)H;   // per lane: 4 halves

    uint2 hv = H2[node * 32 + lane];
    float2 f0 = __half22float2(*(__half2*)&hv.x);
    float2 f1 = __half22float2(*(__half2*)&hv.y);
    float ns = g_nself[node];
    float4 acc = make_float4(ns * f0.x, ns * f0.y, ns * f1.x, ns * f1.y);

    int p = g_rowptr[node];
    int p1 = g_rowptr[node + 1];
    int s = 0; float v = 0.f;
    if (p < p1) { s = g_csrc[p]; v = g_cval[p]; }
    while (p < p1) {
        int sn = 0; float vn = 0.f;
        if (p + 1 < p1) { sn = g_csrc[p + 1]; vn = g_cval[p + 1]; }
        uint2 hs = H2[s * 32 + lane];
        float2 s0 = __half22float2(*(__half2*)&hs.x);
        float2 s1 = __half22float2(*(__half2*)&hs.y);
        acc.x += v * s0.x; acc.y += v * s0.y; acc.z += v * s1.x; acc.w += v * s1.y;
        s = sn; v = vn; p++;
    }
    float4 b = ((const float4*)bias)[lane];
    acc.x = fmaxf(acc.x + b.x, 0.f); acc.y = fmaxf(acc.y + b.y, 0.f);
    acc.z = fmaxf(acc.z + b.z, 0.f); acc.w = fmaxf(acc.w + b.w, 0.f);
    uint2 ov;
    *(__half2*)&ov.x = __floats2half2_rn(acc.x, acc.y);
    *(__half2*)&ov.y = __floats2half2_rn(acc.z, acc.w);
    ((uint2*)O)[node * 32 + lane] = ov;
}

// ---------------- agg2 fused with output GEMM (fp16 gather) -----------------
__global__ void k_agg_out(const __half* __restrict__ H,
                          const float* __restrict__ bias,
                          const float* __restrict__ W3)
{
    __shared__ __align__(16) float Wt[OUTC * F];  // [c][k]
    int tid = threadIdx.x;
    for (int i = tid; i < OUTC * F; i += blockDim.x) {
        int c = i >> 7, k = i & 127;
        Wt[i] = W3[k * OUTC + c];
    }
    __syncthreads();

    int gt = blockIdx.x * blockDim.x + tid;
    int node = gt >> 5;
    int lane = gt & 31;
    const uint2* H2 = (const uint2*)H;

    uint2 hv = H2[node * 32 + lane];
    float2 f0 = __half22float2(*(__half2*)&hv.x);
    float2 f1 = __half22float2(*(__half2*)&hv.y);
    float ns = g_nself[node];
    float4 acc = make_float4(ns * f0.x, ns * f0.y, ns * f1.x, ns * f1.y);

    int p = g_rowptr[node];
    int p1 = g_rowptr[node + 1];
    int s = 0; float v = 0.f;
    if (p < p1) { s = g_csrc[p]; v = g_cval[p]; }
    while (p < p1) {
        int sn = 0; float vn = 0.f;
        if (p + 1 < p1) { sn = g_csrc[p + 1]; vn = g_cval[p + 1]; }
        uint2 hs = H2[s * 32 + lane];
        float2 s0 = __half22float2(*(__half2*)&hs.x);
        float2 s1 = __half22float2(*(__half2*)&hs.y);
        acc.x += v * s0.x; acc.y += v * s0.y; acc.z += v * s1.x; acc.w += v * s1.y;
        s = sn; v = vn; p++;
    }
    float4 b = ((const float4*)bias)[lane];
    acc.x = fmaxf(acc.x + b.x, 0.f); acc.y = fmaxf(acc.y + b.y, 0.f);
    acc.z = fmaxf(acc.z + b.z, 0.f); acc.w = fmaxf(acc.w + b.w, 0.f);

    float o[OUTC];
#pragma unroll
    for (int c = 0; c < OUTC; c++) {
        float4 wv = ((const float4*)Wt)[c * 32 + lane];
        o[c] = acc.x * wv.x + acc.y * wv.y + acc.z * wv.z + acc.w * wv.w;
    }
#pragma unroll
    for (int off = 16; off; off >>= 1)
#pragma unroll
        for (int c = 0; c < OUTC; c++)
            o[c] += __shfl_xor_sync(0xffffffffu, o[c], off);
    if (lane == 0) {
#pragma unroll
        for (int c = 0; c < OUTC; c++) g_h3[node * OUTC + c] = o[c];
    }
}

// ---------------- sparse agg 10-wide + bias + pooling (fused) ---------------
__global__ void k_agg10_pool(const float* __restrict__ b3,
                             const int* __restrict__ batch)
{
    __shared__ float sp[GG * OUTC];
    __shared__ float sc[GG];
    int tid = threadIdx.x;
    for (int j = tid; j < GG * OUTC; j += blockDim.x) sp[j] = 0.f;
    for (int j = tid; j < GG; j += blockDim.x) sc[j] = 0.f;
    __syncthreads();

    int gt = blockIdx.x * blockDim.x + tid;
    int node = gt >> 5;
    int lane = gt & 31;

    float acc = 0.f;
    if (lane < OUTC) acc = g_nself[node] * g_h3[node * OUTC + lane];
    int p = g_rowptr[node];
    int p1 = g_rowptr[node + 1];
    for (; p < p1; p++) {
        int s = g_csrc[p];
        float v = g_cval[p];
        if (lane < OUTC) acc += v * g_h3[s * OUTC + lane];
    }
    int g = batch[node];
    if (lane < OUTC) atomicAdd(&sp[g * OUTC + lane], acc + b3[lane]);
    if (lane == OUTC) atomicAdd(&sc[g], 1.0f);
    __syncthreads();

    for (int j = tid; j < GG * OUTC; j += blockDim.x)
        if (sp[j] != 0.f) atomicAdd(&g_pool[j], sp[j]);
    for (int j = tid; j < GG; j += blockDim.x)
        if (sc[j] != 0.f) atomicAdd(&g_pcnt[j], sc[j]);
}

// ---------------- mean + log_softmax ----------------------------------------
__global__ void k_final(float* __restrict__ out)
{
    int g = threadIdx.x;
    if (g >= GG) return;
    float cnt = fmaxf(g_pcnt[g], 1.0f);
    float v[OUTC];
    float m = -1e30f;
#pragma unroll
    for (int c = 0; c < OUTC; c++) {
        v[c] = g_pool[g * OUTC + c] / cnt;
        m = fmaxf(m, v[c]);
    }
    float s = 0.f;
#pragma unroll
    for (int c = 0; c < OUTC; c++) s += expf(v[c] - m);
    float l = logf(s) + m;
#pragma unroll
    for (int c = 0; c < OUTC; c++) out[g * OUTC + c] = v[c] - l;
}

// ---------------- launch ----------------------------------------------------
extern "C" void kernel_launch(void* const* d_in, const int* in_sizes, int n_in,
                              void* d_out, int out_size)
{
    const float* x     = (const float*)d_in[0];
    const int*   ei    = (const int*)  d_in[1];
    const float* ew    = (const float*)d_in[2];
    const int*   batch = (const int*)  d_in[3];
    const float* W1    = (const float*)d_in[4];
    const float* b1    = (const float*)d_in[5];
    const float* W2    = (const float*)d_in[6];
    const float* b2    = (const float*)d_in[7];
    const float* W3    = (const float*)d_in[8];
    const float* b3    = (const float*)d_in[9];
    float* out = (float*)d_out;

    const int SMEM_MMA = (AF_SIZE + BF_SIZE) * sizeof(uint32_t);  // 49664
    cudaFuncSetAttribute(k_gemm_mma, cudaFuncAttributeMaxDynamicSharedMemorySize, SMEM_MMA);

    __half *h1p, *h2p;
    uint32_t *wf1p, *wf2p;
    cudaGetSymbolAddress((void**)&h1p, g_h1);
    cudaGetSymbolAddress((void**)&h2p, g_h2);
    cudaGetSymbolAddress((void**)&wf1p, g_wf1);
    cudaGetSymbolAddress((void**)&wf2p, g_wf2);

    const int nBlkN = (NN + 255) / 256;          // 196
    const int nBlkE = (EE + 255) / 256;          // 3125
    const int nBlkW = (NN * 32) / 256;           // 6250
    const int nBlkT = (NN + 63) / 64;            // 782 (mma gemm)

    k_zero_wf<<<nBlkN, 256>>>(W1, W2);                           // my 1
    k_deg  <<<nBlkE, 256>>>(ei, ew);                             // my 2
    k_scan1<<<nBlkN, 256>>>();                                   // my 3
    k_gemm_mma<<<nBlkT, 256, SMEM_MMA>>>(x, wf1p, h1p, NN, 0);   // my 4 <- ncu sample
    k_scan23<<<nBlkN, 256>>>();                                  // my 5
    k_fill <<<nBlkE, 256>>>(ei, ew);                             // my 6

    k_agg128<<<nBlkW, 256>>>(h1p, h2p, b1);                      // my 7
    k_gemm_mma<<<nBlkT, 256, SMEM_MMA>>>(h2p, wf2p, h1p, NN, 1); // my 8
    k_agg_out<<<nBlkW, 256>>>(h1p, b2, W3);                      // my 9
    k_agg10_pool<<<nBlkW, 256>>>(b3, batch);                     // my 10
    k_final<<<1, 64>>>(out);                                     // my 11
}

// round 12
// speedup vs baseline: 1.7539x; 1.0415x over previous
#include <cuda_runtime.h>
#include <cuda_fp16.h>
#include <cstdint>
#include <math.h>

#define NN 50000
#define EE 800000
#define F 128
#define OUTC 10
#define GG 64

// fp16-fragment A smem: [g 4][kt 8][132 u32 (33*4 pad)]
#define AF_SIZE (4 * 8 * 132)
// fp16-fragment B smem: [cg 2][ch 4][kt 8][lane 32][4] (u32)
#define BF_SIZE (2 * 4 * 8 * 32 * 4)

// ---------------- scratch (device globals; no allocation allowed) ----------
__device__ __align__(16) float g_deg[NN];
__device__ __align__(16) float g_dinv[NN];
__device__ __align__(16) float g_nself[NN];
__device__ __align__(16) int   g_cnt[NN];
__device__ __align__(16) int   g_fill[NN];
__device__ __align__(16) int   g_rowptr[NN + 1];
__device__ __align__(16) int   g_csrc[EE];
__device__ __align__(16) float g_cval[EE];
__device__ __align__(16) __half g_h1[NN * F];   // fp16 hidden states
__device__ __align__(16) __half g_h2[NN * F];
__device__ __align__(16) float g_h3[NN * OUTC];
__device__ __align__(16) float g_pool[GG * OUTC];
__device__ __align__(16) float g_pcnt[GG];
__device__ __align__(16) int   g_bsum[256];
__device__ __align__(16) uint32_t g_wf1[BF_SIZE];  // W1 in fp16 B-fragment order
__device__ __align__(16) uint32_t g_wf2[BF_SIZE];  // W2 in fp16 B-fragment order

// ---------------- mma helpers -----------------------------------------------
__device__ __forceinline__ void mma_f16(float* d, const uint32_t* a, const uint32_t* b) {
    asm volatile(
        "mma.sync.aligned.m16n8k16.row.col.f32.f16.f16.f32 "
        "{%0,%1,%2,%3}, {%4,%5,%6,%7}, {%8,%9}, {%0,%1,%2,%3};\n"
        : "+f"(d[0]), "+f"(d[1]), "+f"(d[2]), "+f"(d[3])
        : "r"(a[0]), "r"(a[1]), "r"(a[2]), "r"(a[3]), "r"(b[0]), "r"(b[1]));
}
__device__ __forceinline__ uint32_t packh2(float lo, float hi) {
    __half2 h = __floats2half2_rn(lo, hi);
    return *(uint32_t*)&h;
}

// ---------------- init + W-fragment precompute (fp16) -----------------------
__global__ void k_zero_wf(const float* __restrict__ W1, const float* __restrict__ W2) {
    int i = blockIdx.x * blockDim.x + threadIdx.x;
    if (i < NN) { g_deg[i] = 0.f; g_cnt[i] = 0; g_fill[i] = 0; }
    if (i < GG * OUTC) g_pool[i] = 0.f;
    if (i < GG) g_pcnt[i] = 0.f;
    if (i < 2 * BF_SIZE) {                 // BF_SIZE = 8192
        int sel = i >> 13;
        int off = i & (BF_SIZE - 1);
        int pos  = off & 3;
        int lane = (off >> 2) & 31;
        int kt   = (off >> 7) & 7;
        int ch   = (off >> 10) & 3;
        int cg   = (off >> 12) & 1;
        int gid = lane >> 2, tig = lane & 3;
        int nt = 2 * ch + (pos >> 1);
        int bi = pos & 1;
        int col = 64 * cg + 8 * nt + gid;
        int k = 16 * kt + 8 * bi + 2 * tig;
        const float* W = sel ? W2 : W1;
        uint32_t u = packh2(W[k * F + col], W[(k + 1) * F + col]);
        if (sel) g_wf2[off] = u; else g_wf1[off] = u;
    }
}

__global__ void k_deg(const int* __restrict__ ei, const float* __restrict__ ew) {
    int e = blockIdx.x * blockDim.x + threadIdx.x;
    if (e >= EE) return;
    int d = ei[EE + e];
    atomicAdd(&g_deg[d], ew[e]);
    atomicAdd(&g_cnt[d], 1);
}

__global__ void k_scan1() {
    __shared__ int s[256];
    int tid = threadIdx.x;
    int i = blockIdx.x * 256 + tid;
    if (i < NN) {
        float di = rsqrtf(g_deg[i] + 1.0f);
        g_dinv[i] = di;
        g_nself[i] = di * di;
    }
    int v = (i < NN) ? g_cnt[i] : 0;
    s[tid] = v; __syncthreads();
#pragma unroll
    for (int off = 1; off < 256; off <<= 1) {
        int t = (tid >= off) ? s[tid - off] : 0;
        __syncthreads();
        s[tid] += t;
        __syncthreads();
    }
    if (i < NN) g_rowptr[i] = s[tid] - v;
    if (tid == 255) g_bsum[blockIdx.x] = s[255];
}

// fused scan2+scan3
__global__ void k_scan23() {
    __shared__ int wsum[8];
    int tid = threadIdx.x, bid = blockIdx.x;
    int lane = tid & 31, wid = tid >> 5;
    int v = (tid < bid) ? g_bsum[tid] : 0;
#pragma unroll
    for (int off = 16; off; off >>= 1) v += __shfl_xor_sync(0xffffffffu, v, off);
    if (lane == 0) wsum[wid] = v;
    __syncthreads();
    if (tid == 0) {
        int t = 0;
#pragma unroll
        for (int j = 0; j < 8; j++) t += wsum[j];
        wsum[0] = t;
    }
    __syncthreads();
    int pref = wsum[0];
    int i = bid * 256 + tid;
    if (i < NN) g_rowptr[i] += pref;
    if (i == 0) g_rowptr[NN] = EE;
}

__global__ void k_fill(const int* __restrict__ ei, const float* __restrict__ ew) {
    int e = blockIdx.x * blockDim.x + threadIdx.x;
    if (e >= EE) return;
    int s = ei[e];
    int d = ei[EE + e];
    float nv = g_dinv[s] * ew[e] * g_dinv[d];
    int p = g_rowptr[d] + atomicAdd(&g_fill[d], 1);
    g_csrc[p] = s;
    g_cval[p] = nv;
}

// ---------------- fp16 mma GEMM, fragment-major smem, 2 row-tiles/CTA -------
// CTA covers 128 rows as two 64-row tiles reusing staged B. 8 warps.
__global__ void __launch_bounds__(256) k_gemm_mma(
    const void* __restrict__ Xv, const uint32_t* __restrict__ Wf,
    __half* __restrict__ Y, int nrows, int x_is_half)
{
    extern __shared__ uint32_t sm[];
    uint32_t* Af = sm;              // AF_SIZE
    uint32_t* Bf = sm + AF_SIZE;    // BF_SIZE
    int tid = threadIdx.x;

    // stage B once: straight fragment-order copy (coalesced, L2-resident)
#pragma unroll
    for (int it = 0; it < 8; it++) {
        int i = (tid + it * 256) * 4;
        *(uint4*)&Bf[i] = *(const uint4*)&Wf[i];
    }

    const float*  Xf = (const float*)Xv;
    const uint32_t* Xh = (const uint32_t*)Xv;   // fp16 pairs, 64 per row

    int wid = tid >> 5, lane = tid & 31;
    int gid = lane >> 2, tig = lane & 3;
    int mg = wid >> 1;            // row group 0..3
    int cg = wid & 1;             // col half 0..1

#pragma unroll 1
    for (int half_t = 0; half_t < 2; half_t++) {
        int row0 = blockIdx.x * 128 + half_t * 64;
        // stage A: fp16 fragment scatter. 4096 u32 total, 16 per thread.
        __syncthreads();   // protect Af from previous iteration's readers
#pragma unroll
        for (int it = 0; it < 16; it++) {
            int j = tid + it * 256;            // u32 index 0..4095
            int aidx = j & 3;
            int lfr  = (j >> 2) & 31;
            int kt   = (j >> 7) & 7;
            int g    = (j >> 10) & 3;
            int gg = lfr >> 2, tg = lfr & 3;
            int row = row0 + g * 16 + gg + 8 * (aidx & 1);
            int k = 16 * kt + 8 * (aidx >> 1) + 2 * tg;
            uint32_t u = 0;
            if (row < nrows) {
                if (x_is_half) {
                    u = Xh[row * 64 + (k >> 1)];
                } else {
                    float2 v = *(const float2*)&Xf[row * F + k];
                    u = packh2(v.x, v.y);
                }
            }
            Af[(g * 8 + kt) * 132 + lfr * 4 + aidx] = u;
        }
        __syncthreads();

        float acc[8][4];
#pragma unroll
        for (int nt = 0; nt < 8; nt++)
#pragma unroll
            for (int j = 0; j < 4; j++) acc[nt][j] = 0.f;

#pragma unroll
        for (int kt = 0; kt < 8; kt++) {
            uint32_t a[4];
            *(uint4*)a = *(const uint4*)&Af[(mg * 8 + kt) * 132 + lane * 4];
#pragma unroll
            for (int ch = 0; ch < 4; ch++) {
                uint32_t b[4];
                *(uint4*)b = *(const uint4*)&Bf[(((cg * 4 + ch) * 8 + kt) * 32 + lane) * 4];
                mma_f16(acc[2 * ch],     a, &b[0]);
                mma_f16(acc[2 * ch + 1], a, &b[2]);
            }
        }

        int r0 = row0 + mg * 16 + gid;
        int r1 = r0 + 8;
        __half2* Y2 = (__half2*)Y;
#pragma unroll
        for (int nt = 0; nt < 8; nt++) {
            int c = cg * 64 + nt * 8 + tig * 2;
            if (r0 < nrows) Y2[r0 * 64 + (c >> 1)] = __floats2half2_rn(acc[nt][0], acc[nt][1]);
            if (r1 < nrows) Y2[r1 * 64 + (c >> 1)] = __floats2half2_rn(acc[nt][2], acc[nt][3]);
        }
    }
}

// ---------------- sparse aggregation, 128-wide fp16 (warp per node) ---------
__global__ void k_agg128(const __half* __restrict__ H, __half* __restrict__ O,
                         const float* __restrict__ bias)
{
    int gt = blockIdx.x * blockDim.x + threadIdx.x;
    int node = gt >> 5;
    int lane = gt & 31;
    const uint2* H2 = (const uint2*)H;   // per lane: 4 halves

    uint2 hv = H2[node * 32 + lane];
    float2 f0 = __half22float2(*(__half2*)&hv.x);
    float2 f1 = __half22float2(*(__half2*)&hv.y);
    float ns = g_nself[node];
    float4 acc = make_float4(ns * f0.x, ns * f0.y, ns * f1.x, ns * f1.y);

    int p = g_rowptr[node];
    int p1 = g_rowptr[node + 1];
    // unrolled by 2 for MLP
    for (; p + 1 < p1; p += 2) {
        int sa = g_csrc[p],     sb = g_csrc[p + 1];
        float va = g_cval[p],   vb = g_cval[p + 1];
        uint2 ha = H2[sa * 32 + lane];
        uint2 hb = H2[sb * 32 + lane];
        float2 a0 = __half22float2(*(__half2*)&ha.x);
        float2 a1 = __half22float2(*(__half2*)&ha.y);
        float2 b0 = __half22float2(*(__half2*)&hb.x);
        float2 b1 = __half22float2(*(__half2*)&hb.y);
        acc.x += va * a0.x + vb * b0.x;
        acc.y += va * a0.y + vb * b0.y;
        acc.z += va * a1.x + vb * b1.x;
        acc.w += va * a1.y + vb * b1.y;
    }
    if (p < p1) {
        int s = g_csrc[p]; float v = g_cval[p];
        uint2 hs = H2[s * 32 + lane];
        float2 s0 = __half22float2(*(__half2*)&hs.x);
        float2 s1 = __half22float2(*(__half2*)&hs.y);
        acc.x += v * s0.x; acc.y += v * s0.y; acc.z += v * s1.x; acc.w += v * s1.y;
    }
    float4 b = ((const float4*)bias)[lane];
    acc.x = fmaxf(acc.x + b.x, 0.f); acc.y = fmaxf(acc.y + b.y, 0.f);
    acc.z = fmaxf(acc.z + b.z, 0.f); acc.w = fmaxf(acc.w + b.w, 0.f);
    uint2 ov;
    *(__half2*)&ov.x = __floats2half2_rn(acc.x, acc.y);
    *(__half2*)&ov.y = __floats2half2_rn(acc.z, acc.w);
    ((uint2*)O)[node * 32 + lane] = ov;
}

// ---------------- agg2 fused with output GEMM (fp16 gather) -----------------
__global__ void k_agg_out(const __half* __restrict__ H,
                          const float* __restrict__ bias,
                          const float* __restrict__ W3)
{
    __shared__ __align__(16) float Wt[OUTC * F];  // [c][k]
    int tid = threadIdx.x;
    for (int i = tid; i < OUTC * F; i += blockDim.x) {
        int c = i >> 7, k = i & 127;
        Wt[i] = W3[k * OUTC + c];
    }
    __syncthreads();

    int gt = blockIdx.x * blockDim.x + tid;
    int node = gt >> 5;
    int lane = gt & 31;
    const uint2* H2 = (const uint2*)H;

    uint2 hv = H2[node * 32 + lane];
    float2 f0 = __half22float2(*(__half2*)&hv.x);
    float2 f1 = __half22float2(*(__half2*)&hv.y);
    float ns = g_nself[node];
    float4 acc = make_float4(ns * f0.x, ns * f0.y, ns * f1.x, ns * f1.y);

    int p = g_rowptr[node];
    int p1 = g_rowptr[node + 1];
    for (; p + 1 < p1; p += 2) {
        int sa = g_csrc[p],     sb = g_csrc[p + 1];
        float va = g_cval[p],   vb = g_cval[p + 1];
        uint2 ha = H2[sa * 32 + lane];
        uint2 hb = H2[sb * 32 + lane];
        float2 a0 = __half22float2(*(__half2*)&ha.x);
        float2 a1 = __half22float2(*(__half2*)&ha.y);
        float2 b0 = __half22float2(*(__half2*)&hb.x);
        float2 b1 = __half22float2(*(__half2*)&hb.y);
        acc.x += va * a0.x + vb * b0.x;
        acc.y += va * a0.y + vb * b0.y;
        acc.z += va * a1.x + vb * b1.x;
        acc.w += va * a1.y + vb * b1.y;
    }
    if (p < p1) {
        int s = g_csrc[p]; float v = g_cval[p];
        uint2 hs = H2[s * 32 + lane];
        float2 s0 = __half22float2(*(__half2*)&hs.x);
        float2 s1 = __half22float2(*(__half2*)&hs.y);
        acc.x += v * s0.x; acc.y += v * s0.y; acc.z += v * s1.x; acc.w += v * s1.y;
    }
    float4 b = ((const float4*)bias)[lane];
    acc.x = fmaxf(acc.x + b.x, 0.f); acc.y = fmaxf(acc.y + b.y, 0.f);
    acc.z = fmaxf(acc.z + b.z, 0.f); acc.w = fmaxf(acc.w + b.w, 0.f);

    float o[OUTC];
#pragma unroll
    for (int c = 0; c < OUTC; c++) {
        float4 wv = ((const float4*)Wt)[c * 32 + lane];
        o[c] = acc.x * wv.x + acc.y * wv.y + acc.z * wv.z + acc.w * wv.w;
    }
#pragma unroll
    for (int off = 16; off; off >>= 1)
#pragma unroll
        for (int c = 0; c < OUTC; c++)
            o[c] += __shfl_xor_sync(0xffffffffu, o[c], off);
    if (lane == 0) {
#pragma unroll
        for (int c = 0; c < OUTC; c++) g_h3[node * OUTC + c] = o[c];
    }
}

// ---------------- sparse agg 10-wide + bias + pooling (fused) ---------------
__global__ void k_agg10_pool(const float* __restrict__ b3,
                             const int* __restrict__ batch)
{
    __shared__ float sp[GG * OUTC];
    __shared__ float sc[GG];
    int tid = threadIdx.x;
    for (int j = tid; j < GG * OUTC; j += blockDim.x) sp[j] = 0.f;
    for (int j = tid; j < GG; j += blockDim.x) sc[j] = 0.f;
    __syncthreads();

    int gt = blockIdx.x * blockDim.x + tid;
    int node = gt >> 5;
    int lane = gt & 31;

    float acc = 0.f;
    if (lane < OUTC) acc = g_nself[node] * g_h3[node * OUTC + lane];
    int p = g_rowptr[node];
    int p1 = g_rowptr[node + 1];
    for (; p < p1; p++) {
        int s = g_csrc[p];
        float v = g_cval[p];
        if (lane < OUTC) acc += v * g_h3[s * OUTC + lane];
    }
    int g = batch[node];
    if (lane < OUTC) atomicAdd(&sp[g * OUTC + lane], acc + b3[lane]);
    if (lane == OUTC) atomicAdd(&sc[g], 1.0f);
    __syncthreads();

    for (int j = tid; j < GG * OUTC; j += blockDim.x)
        if (sp[j] != 0.f) atomicAdd(&g_pool[j], sp[j]);
    for (int j = tid; j < GG; j += blockDim.x)
        if (sc[j] != 0.f) atomicAdd(&g_pcnt[j], sc[j]);
}

// ---------------- mean + log_softmax ----------------------------------------
__global__ void k_final(float* __restrict__ out)
{
    int g = threadIdx.x;
    if (g >= GG) return;
    float cnt = fmaxf(g_pcnt[g], 1.0f);
    float v[OUTC];
    float m = -1e30f;
#pragma unroll
    for (int c = 0; c < OUTC; c++) {
        v[c] = g_pool[g * OUTC + c] / cnt;
        m = fmaxf(m, v[c]);
    }
    float s = 0.f;
#pragma unroll
    for (int c = 0; c < OUTC; c++) s += expf(v[c] - m);
    float l = logf(s) + m;
#pragma unroll
    for (int c = 0; c < OUTC; c++) out[g * OUTC + c] = v[c] - l;
}

// ---------------- launch ----------------------------------------------------
extern "C" void kernel_launch(void* const* d_in, const int* in_sizes, int n_in,
                              void* d_out, int out_size)
{
    const float* x     = (const float*)d_in[0];
    const int*   ei    = (const int*)  d_in[1];
    const float* ew    = (const float*)d_in[2];
    const int*   batch = (const int*)  d_in[3];
    const float* W1    = (const float*)d_in[4];
    const float* b1    = (const float*)d_in[5];
    const float* W2    = (const float*)d_in[6];
    const float* b2    = (const float*)d_in[7];
    const float* W3    = (const float*)d_in[8];
    const float* b3    = (const float*)d_in[9];
    float* out = (float*)d_out;

    const int SMEM_MMA = (AF_SIZE + BF_SIZE) * sizeof(uint32_t);  // 49664
    cudaFuncSetAttribute(k_gemm_mma, cudaFuncAttributeMaxDynamicSharedMemorySize, SMEM_MMA);

    __half *h1p, *h2p;
    uint32_t *wf1p, *wf2p;
    cudaGetSymbolAddress((void**)&h1p, g_h1);
    cudaGetSymbolAddress((void**)&h2p, g_h2);
    cudaGetSymbolAddress((void**)&wf1p, g_wf1);
    cudaGetSymbolAddress((void**)&wf2p, g_wf2);

    const int nBlkN = (NN + 255) / 256;          // 196
    const int nBlkE = (EE + 255) / 256;          // 3125
    const int nBlkW = (NN * 32) / 256;           // 6250
    const int nBlkT = (NN + 127) / 128;          // 391 (mma gemm, 2 tiles/CTA)

    k_zero_wf<<<nBlkN, 256>>>(W1, W2);                           // my 1
    k_deg  <<<nBlkE, 256>>>(ei, ew);                             // my 2
    k_scan1<<<nBlkN, 256>>>();                                   // my 3
    k_gemm_mma<<<nBlkT, 256, SMEM_MMA>>>(x, wf1p, h1p, NN, 0);   // my 4 <- ncu sample
    k_scan23<<<nBlkN, 256>>>();                                  // my 5
    k_fill <<<nBlkE, 256>>>(ei, ew);                             // my 6

    k_agg128<<<nBlkW, 256>>>(h1p, h2p, b1);                      // my 7
    k_gemm_mma<<<nBlkT, 256, SMEM_MMA>>>(h2p, wf2p, h1p, NN, 1); // my 8
    k_agg_out<<<nBlkW, 256>>>(h1p, b2, W3);                      // my 9
    k_agg10_pool<<<nBlkW, 256>>>(b3, batch);                     // my 10
    k_final<<<1, 64>>>(out);                                     // my 11
}

// round 13
// speedup vs baseline: 1.7783x; 1.0139x over previous
#include <cuda_runtime.h>
#include <cuda_fp16.h>
#include <cstdint>
#include <math.h>

#define NN 50000
#define EE 800000
#define F 128
#define OUTC 10
#define GG 64

// fp16-fragment A smem: [g 4][kt 8][132 u32 (33*4 pad)]
#define AF_SIZE (4 * 8 * 132)
// fp16-fragment B smem: [cg 2][ch 4][kt 8][lane 32][4] (u32)
#define BF_SIZE (2 * 4 * 8 * 32 * 4)

// ---------------- scratch (device globals; no allocation allowed) ----------
__device__ __align__(16) float g_deg[NN];
__device__ __align__(16) float g_dinv[NN];
__device__ __align__(16) float g_nself[NN];
__device__ __align__(16) int   g_cnt[NN];
__device__ __align__(16) int   g_fill[NN];
__device__ __align__(16) int   g_rowptr[NN + 1];
__device__ __align__(16) int   g_csrc[EE];
__device__ __align__(16) float g_cval[EE];
__device__ __align__(16) __half g_h1[NN * F];   // fp16 hidden states
__device__ __align__(16) __half g_h2[NN * F];
__device__ __align__(16) float g_h3[NN * OUTC];
__device__ __align__(16) float g_pool[GG * OUTC];
__device__ __align__(16) float g_pcnt[GG];
__device__ __align__(16) int   g_bsum[256];
__device__ __align__(16) uint32_t g_wf1[BF_SIZE];  // W1 in fp16 B-fragment order
__device__ __align__(16) uint32_t g_wf2[BF_SIZE];  // W2 in fp16 B-fragment order

// ---------------- mma helpers -----------------------------------------------
__device__ __forceinline__ void mma_f16(float* d, const uint32_t* a, const uint32_t* b) {
    asm volatile(
        "mma.sync.aligned.m16n8k16.row.col.f32.f16.f16.f32 "
        "{%0,%1,%2,%3}, {%4,%5,%6,%7}, {%8,%9}, {%0,%1,%2,%3};\n"
        : "+f"(d[0]), "+f"(d[1]), "+f"(d[2]), "+f"(d[3])
        : "r"(a[0]), "r"(a[1]), "r"(a[2]), "r"(a[3]), "r"(b[0]), "r"(b[1]));
}
__device__ __forceinline__ uint32_t packh2(float lo, float hi) {
    __half2 h = __floats2half2_rn(lo, hi);
    return *(uint32_t*)&h;
}

// ---------------- init (branch A) -------------------------------------------
__global__ void k_zero() {
    int i = blockIdx.x * blockDim.x + threadIdx.x;
    if (i < NN) { g_deg[i] = 0.f; g_cnt[i] = 0; g_fill[i] = 0; }
    if (i < GG * OUTC) g_pool[i] = 0.f;
    if (i < GG) g_pcnt[i] = 0.f;
}

// ---------------- W-fragment precompute (branch B) --------------------------
__global__ void k_wf(const float* __restrict__ W1, const float* __restrict__ W2) {
    int i = blockIdx.x * blockDim.x + threadIdx.x;
    if (i >= 2 * BF_SIZE) return;          // BF_SIZE = 8192
    int sel = i >> 13;
    int off = i & (BF_SIZE - 1);
    int pos  = off & 3;
    int lane = (off >> 2) & 31;
    int kt   = (off >> 7) & 7;
    int ch   = (off >> 10) & 3;
    int cg   = (off >> 12) & 1;
    int gid = lane >> 2, tig = lane & 3;
    int nt = 2 * ch + (pos >> 1);
    int bi = pos & 1;
    int col = 64 * cg + 8 * nt + gid;
    int k = 16 * kt + 8 * bi + 2 * tig;
    const float* W = sel ? W2 : W1;
    uint32_t u = packh2(W[k * F + col], W[(k + 1) * F + col]);
    if (sel) g_wf2[off] = u; else g_wf1[off] = u;
}

__global__ void k_deg(const int* __restrict__ ei, const float* __restrict__ ew) {
    int e = blockIdx.x * blockDim.x + threadIdx.x;
    if (e >= EE) return;
    int d = ei[EE + e];
    atomicAdd(&g_deg[d], ew[e]);
    atomicAdd(&g_cnt[d], 1);
}

__global__ void k_scan1() {
    __shared__ int s[256];
    int tid = threadIdx.x;
    int i = blockIdx.x * 256 + tid;
    if (i < NN) {
        float di = rsqrtf(g_deg[i] + 1.0f);
        g_dinv[i] = di;
        g_nself[i] = di * di;
    }
    int v = (i < NN) ? g_cnt[i] : 0;
    s[tid] = v; __syncthreads();
#pragma unroll
    for (int off = 1; off < 256; off <<= 1) {
        int t = (tid >= off) ? s[tid - off] : 0;
        __syncthreads();
        s[tid] += t;
        __syncthreads();
    }
    if (i < NN) g_rowptr[i] = s[tid] - v;
    if (tid == 255) g_bsum[blockIdx.x] = s[255];
}

// fused scan2+scan3
__global__ void k_scan23() {
    __shared__ int wsum[8];
    int tid = threadIdx.x, bid = blockIdx.x;
    int lane = tid & 31, wid = tid >> 5;
    int v = (tid < bid) ? g_bsum[tid] : 0;
#pragma unroll
    for (int off = 16; off; off >>= 1) v += __shfl_xor_sync(0xffffffffu, v, off);
    if (lane == 0) wsum[wid] = v;
    __syncthreads();
    if (tid == 0) {
        int t = 0;
#pragma unroll
        for (int j = 0; j < 8; j++) t += wsum[j];
        wsum[0] = t;
    }
    __syncthreads();
    int pref = wsum[0];
    int i = bid * 256 + tid;
    if (i < NN) g_rowptr[i] += pref;
    if (i == 0) g_rowptr[NN] = EE;
}

__global__ void k_fill(const int* __restrict__ ei, const float* __restrict__ ew) {
    int e = blockIdx.x * blockDim.x + threadIdx.x;
    if (e >= EE) return;
    int s = ei[e];
    int d = ei[EE + e];
    float nv = g_dinv[s] * ew[e] * g_dinv[d];
    int p = g_rowptr[d] + atomicAdd(&g_fill[d], 1);
    g_csrc[p] = s;
    g_cval[p] = nv;
}

// ---------------- fp16 mma GEMM, fragment-major smem, 2 row-tiles/CTA -------
__global__ void __launch_bounds__(256) k_gemm_mma(
    const void* __restrict__ Xv, const uint32_t* __restrict__ Wf,
    __half* __restrict__ Y, int nrows, int x_is_half)
{
    extern __shared__ uint32_t sm[];
    uint32_t* Af = sm;              // AF_SIZE
    uint32_t* Bf = sm + AF_SIZE;    // BF_SIZE
    int tid = threadIdx.x;

    // stage B once: straight fragment-order copy (coalesced, L2-resident)
#pragma unroll
    for (int it = 0; it < 8; it++) {
        int i = (tid + it * 256) * 4;
        *(uint4*)&Bf[i] = *(const uint4*)&Wf[i];
    }

    const float*  Xf = (const float*)Xv;
    const uint32_t* Xh = (const uint32_t*)Xv;   // fp16 pairs, 64 per row

    int wid = tid >> 5, lane = tid & 31;
    int gid = lane >> 2, tig = lane & 3;
    int mg = wid >> 1;            // row group 0..3
    int cg = wid & 1;             // col half 0..1

#pragma unroll 1
    for (int half_t = 0; half_t < 2; half_t++) {
        int row0 = blockIdx.x * 128 + half_t * 64;
        __syncthreads();   // protect Af from previous iteration's readers
#pragma unroll
        for (int it = 0; it < 16; it++) {
            int j = tid + it * 256;            // u32 index 0..4095
            int aidx = j & 3;
            int lfr  = (j >> 2) & 31;
            int kt   = (j >> 7) & 7;
            int g    = (j >> 10) & 3;
            int gg = lfr >> 2, tg = lfr & 3;
            int row = row0 + g * 16 + gg + 8 * (aidx & 1);
            int k = 16 * kt + 8 * (aidx >> 1) + 2 * tg;
            uint32_t u = 0;
            if (row < nrows) {
                if (x_is_half) {
                    u = Xh[row * 64 + (k >> 1)];
                } else {
                    float2 v = *(const float2*)&Xf[row * F + k];
                    u = packh2(v.x, v.y);
                }
            }
            Af[(g * 8 + kt) * 132 + lfr * 4 + aidx] = u;
        }
        __syncthreads();

        float acc[8][4];
#pragma unroll
        for (int nt = 0; nt < 8; nt++)
#pragma unroll
            for (int j = 0; j < 4; j++) acc[nt][j] = 0.f;

#pragma unroll
        for (int kt = 0; kt < 8; kt++) {
            uint32_t a[4];
            *(uint4*)a = *(const uint4*)&Af[(mg * 8 + kt) * 132 + lane * 4];
#pragma unroll
            for (int ch = 0; ch < 4; ch++) {
                uint32_t b[4];
                *(uint4*)b = *(const uint4*)&Bf[(((cg * 4 + ch) * 8 + kt) * 32 + lane) * 4];
                mma_f16(acc[2 * ch],     a, &b[0]);
                mma_f16(acc[2 * ch + 1], a, &b[2]);
            }
        }

        int r0 = row0 + mg * 16 + gid;
        int r1 = r0 + 8;
        __half2* Y2 = (__half2*)Y;
#pragma unroll
        for (int nt = 0; nt < 8; nt++) {
            int c = cg * 64 + nt * 8 + tig * 2;
            if (r0 < nrows) Y2[r0 * 64 + (c >> 1)] = __floats2half2_rn(acc[nt][0], acc[nt][1]);
            if (r1 < nrows) Y2[r1 * 64 + (c >> 1)] = __floats2half2_rn(acc[nt][2], acc[nt][3]);
        }
    }
}

// ---------------- sparse aggregation, 128-wide fp16 (warp per node) ---------
__global__ void k_agg128(const __half* __restrict__ H, __half* __restrict__ O,
                         const float* __restrict__ bias)
{
    int gt = blockIdx.x * blockDim.x + threadIdx.x;
    int node = gt >> 5;
    int lane = gt & 31;
    const uint2* H2 = (const uint2*)H;   // per lane: 4 halves

    uint2 hv = H2[node * 32 + lane];
    float2 f0 = __half22float2(*(__half2*)&hv.x);
    float2 f1 = __half22float2(*(__half2*)&hv.y);
    float ns = g_nself[node];
    float4 acc = make_float4(ns * f0.x, ns * f0.y, ns * f1.x, ns * f1.y);

    int p = g_rowptr[node];
    int p1 = g_rowptr[node + 1];
    for (; p + 1 < p1; p += 2) {
        int sa = g_csrc[p],     sb = g_csrc[p + 1];
        float va = g_cval[p],   vb = g_cval[p + 1];
        uint2 ha = H2[sa * 32 + lane];
        uint2 hb = H2[sb * 32 + lane];
        float2 a0 = __half22float2(*(__half2*)&ha.x);
        float2 a1 = __half22float2(*(__half2*)&ha.y);
        float2 b0 = __half22float2(*(__half2*)&hb.x);
        float2 b1 = __half22float2(*(__half2*)&hb.y);
        acc.x += va * a0.x + vb * b0.x;
        acc.y += va * a0.y + vb * b0.y;
        acc.z += va * a1.x + vb * b1.x;
        acc.w += va * a1.y + vb * b1.y;
    }
    if (p < p1) {
        int s = g_csrc[p]; float v = g_cval[p];
        uint2 hs = H2[s * 32 + lane];
        float2 s0 = __half22float2(*(__half2*)&hs.x);
        float2 s1 = __half22float2(*(__half2*)&hs.y);
        acc.x += v * s0.x; acc.y += v * s0.y; acc.z += v * s1.x; acc.w += v * s1.y;
    }
    float4 b = ((const float4*)bias)[lane];
    acc.x = fmaxf(acc.x + b.x, 0.f); acc.y = fmaxf(acc.y + b.y, 0.f);
    acc.z = fmaxf(acc.z + b.z, 0.f); acc.w = fmaxf(acc.w + b.w, 0.f);
    uint2 ov;
    *(__half2*)&ov.x = __floats2half2_rn(acc.x, acc.y);
    *(__half2*)&ov.y = __floats2half2_rn(acc.z, acc.w);
    ((uint2*)O)[node * 32 + lane] = ov;
}

// ---------------- agg2 fused with output GEMM (fp16 gather) -----------------
__global__ void k_agg_out(const __half* __restrict__ H,
                          const float* __restrict__ bias,
                          const float* __restrict__ W3)
{
    __shared__ __align__(16) float Wt[OUTC * F];  // [c][k]
    int tid = threadIdx.x;
    for (int i = tid; i < OUTC * F; i += blockDim.x) {
        int c = i >> 7, k = i & 127;
        Wt[i] = W3[k * OUTC + c];
    }
    __syncthreads();

    int gt = blockIdx.x * blockDim.x + tid;
    int node = gt >> 5;
    int lane = gt & 31;
    const uint2* H2 = (const uint2*)H;

    uint2 hv = H2[node * 32 + lane];
    float2 f0 = __half22float2(*(__half2*)&hv.x);
    float2 f1 = __half22float2(*(__half2*)&hv.y);
    float ns = g_nself[node];
    float4 acc = make_float4(ns * f0.x, ns * f0.y, ns * f1.x, ns * f1.y);

    int p = g_rowptr[node];
    int p1 = g_rowptr[node + 1];
    for (; p + 1 < p1; p += 2) {
        int sa = g_csrc[p],     sb = g_csrc[p + 1];
        float va = g_cval[p],   vb = g_cval[p + 1];
        uint2 ha = H2[sa * 32 + lane];
        uint2 hb = H2[sb * 32 + lane];
        float2 a0 = __half22float2(*(__half2*)&ha.x);
        float2 a1 = __half22float2(*(__half2*)&ha.y);
        float2 b0 = __half22float2(*(__half2*)&hb.x);
        float2 b1 = __half22float2(*(__half2*)&hb.y);
        acc.x += va * a0.x + vb * b0.x;
        acc.y += va * a0.y + vb * b0.y;
        acc.z += va * a1.x + vb * b1.x;
        acc.w += va * a1.y + vb * b1.y;
    }
    if (p < p1) {
        int s = g_csrc[p]; float v = g_cval[p];
        uint2 hs = H2[s * 32 + lane];
        float2 s0 = __half22float2(*(__half2*)&hs.x);
        float2 s1 = __half22float2(*(__half2*)&hs.y);
        acc.x += v * s0.x; acc.y += v * s0.y; acc.z += v * s1.x; acc.w += v * s1.y;
    }
    float4 b = ((const float4*)bias)[lane];
    acc.x = fmaxf(acc.x + b.x, 0.f); acc.y = fmaxf(acc.y + b.y, 0.f);
    acc.z = fmaxf(acc.z + b.z, 0.f); acc.w = fmaxf(acc.w + b.w, 0.f);

    float o[OUTC];
#pragma unroll
    for (int c = 0; c < OUTC; c++) {
        float4 wv = ((const float4*)Wt)[c * 32 + lane];
        o[c] = acc.x * wv.x + acc.y * wv.y + acc.z * wv.z + acc.w * wv.w;
    }
#pragma unroll
    for (int off = 16; off; off >>= 1)
#pragma unroll
        for (int c = 0; c < OUTC; c++)
            o[c] += __shfl_xor_sync(0xffffffffu, o[c], off);
    if (lane == 0) {
#pragma unroll
        for (int c = 0; c < OUTC; c++) g_h3[node * OUTC + c] = o[c];
    }
}

// ---------------- sparse agg 10-wide + bias + pooling (fused) ---------------
__global__ void k_agg10_pool(const float* __restrict__ b3,
                             const int* __restrict__ batch)
{
    __shared__ float sp[GG * OUTC];
    __shared__ float sc[GG];
    int tid = threadIdx.x;
    for (int j = tid; j < GG * OUTC; j += blockDim.x) sp[j] = 0.f;
    for (int j = tid; j < GG; j += blockDim.x) sc[j] = 0.f;
    __syncthreads();

    int gt = blockIdx.x * blockDim.x + tid;
    int node = gt >> 5;
    int lane = gt & 31;

    float acc = 0.f;
    if (lane < OUTC) acc = g_nself[node] * g_h3[node * OUTC + lane];
    int p = g_rowptr[node];
    int p1 = g_rowptr[node + 1];
    for (; p < p1; p++) {
        int s = g_csrc[p];
        float v = g_cval[p];
        if (lane < OUTC) acc += v * g_h3[s * OUTC + lane];
    }
    int g = batch[node];
    if (lane < OUTC) atomicAdd(&sp[g * OUTC + lane], acc + b3[lane]);
    if (lane == OUTC) atomicAdd(&sc[g], 1.0f);
    __syncthreads();

    for (int j = tid; j < GG * OUTC; j += blockDim.x)
        if (sp[j] != 0.f) atomicAdd(&g_pool[j], sp[j]);
    for (int j = tid; j < GG; j += blockDim.x)
        if (sc[j] != 0.f) atomicAdd(&g_pcnt[j], sc[j]);
}

// ---------------- mean + log_softmax ----------------------------------------
__global__ void k_final(float* __restrict__ out)
{
    int g = threadIdx.x;
    if (g >= GG) return;
    float cnt = fmaxf(g_pcnt[g], 1.0f);
    float v[OUTC];
    float m = -1e30f;
#pragma unroll
    for (int c = 0; c < OUTC; c++) {
        v[c] = g_pool[g * OUTC + c] / cnt;
        m = fmaxf(m, v[c]);
    }
    float s = 0.f;
#pragma unroll
    for (int c = 0; c < OUTC; c++) s += expf(v[c] - m);
    float l = logf(s) + m;
#pragma unroll
    for (int c = 0; c < OUTC; c++) out[g * OUTC + c] = v[c] - l;
}

// ---------------- launch ----------------------------------------------------
extern "C" void kernel_launch(void* const* d_in, const int* in_sizes, int n_in,
                              void* d_out, int out_size)
{
    const float* x     = (const float*)d_in[0];
    const int*   ei    = (const int*)  d_in[1];
    const float* ew    = (const float*)d_in[2];
    const int*   batch = (const int*)  d_in[3];
    const float* W1    = (const float*)d_in[4];
    const float* b1    = (const float*)d_in[5];
    const float* W2    = (const float*)d_in[6];
    const float* b2    = (const float*)d_in[7];
    const float* W3    = (const float*)d_in[8];
    const float* b3    = (const float*)d_in[9];
    float* out = (float*)d_out;

    const int SMEM_MMA = (AF_SIZE + BF_SIZE) * sizeof(uint32_t);  // 49664
    cudaFuncSetAttribute(k_gemm_mma, cudaFuncAttributeMaxDynamicSharedMemorySize, SMEM_MMA);

    // lazily-created side stream + fork/join events (no device allocation)
    static cudaStream_t s2 = nullptr;
    static cudaEvent_t ev_fork = nullptr, ev_join = nullptr;
    if (!s2) {
        cudaStreamCreateWithFlags(&s2, cudaStreamNonBlocking);
        cudaEventCreateWithFlags(&ev_fork, cudaEventDisableTiming);
        cudaEventCreateWithFlags(&ev_join, cudaEventDisableTiming);
    }

    __half *h1p, *h2p;
    uint32_t *wf1p, *wf2p;
    cudaGetSymbolAddress((void**)&h1p, g_h1);
    cudaGetSymbolAddress((void**)&h2p, g_h2);
    cudaGetSymbolAddress((void**)&wf1p, g_wf1);
    cudaGetSymbolAddress((void**)&wf2p, g_wf2);

    const int nBlkN = (NN + 255) / 256;          // 196
    const int nBlkE = (EE + 255) / 256;          // 3125
    const int nBlkW = (NN * 32) / 256;           // 6250
    const int nBlkT = (NN + 127) / 128;          // 391 (mma gemm, 2 tiles/CTA)

    // fork: branch B (s2) = wf + gemm1 ; branch A (default) = graph preproc
    cudaEventRecord(ev_fork, 0);
    cudaStreamWaitEvent(s2, ev_fork, 0);

    k_zero<<<nBlkN, 256>>>();                                        // A
    k_deg <<<nBlkE, 256>>>(ei, ew);                                  // A
    k_wf  <<<(2 * BF_SIZE + 255) / 256, 256, 0, s2>>>(W1, W2);       // B
    k_gemm_mma<<<nBlkT, 256, SMEM_MMA, s2>>>(x, wf1p, h1p, NN, 0);   // B (4th launch -> ncu)
    cudaEventRecord(ev_join, s2);
    k_scan1<<<nBlkN, 256>>>();                                       // A
    k_scan23<<<nBlkN, 256>>>();                                      // A
    k_fill <<<nBlkE, 256>>>(ei, ew);                                 // A

    cudaStreamWaitEvent(0, ev_join, 0);   // join: agg128 needs fill + gemm1

    k_agg128<<<nBlkW, 256>>>(h1p, h2p, b1);
    k_gemm_mma<<<nBlkT, 256, SMEM_MMA>>>(h2p, wf2p, h1p, NN, 1);
    k_agg_out<<<nBlkW, 256>>>(h1p, b2, W3);
    k_agg10_pool<<<nBlkW, 256>>>(b3, batch);
    k_final<<<1, 64>>>(out);
}